// round 14
// baseline (speedup 1.0000x reference)
#include <cuda_runtime.h>
#include <cstdint>

// S_LSTM: 4-layer elementwise LSTM over a 1024x1024 broadcast grid, T=16.
// One thread per (r,c). R13 = R12 champion (l-outer/t-inner, f32x2 gate
// pairing, L2-prefetched weights, layer-0 specialized) + micro-trims:
//   - sx pre-packed as u64 (xt,xt): one less ALU pack per layer-step
//   - next layer's weight lines prefetched into L1 during current t-loop

#define TT 16
#define HDIM 1024
#define NL 4
#define HH (HDIM * HDIM)

#define FMA2(d, a, b, c) asm("fma.rn.f32x2 %0, %1, %2, %3;" : "=l"(d) : "l"(a), "l"(b), "l"(c))
#define MUL2(d, a, b)    asm("mul.rn.f32x2 %0, %1, %2;"     : "=l"(d) : "l"(a), "l"(b))
#define PF_L2(p)         asm volatile("prefetch.global.L2 [%0];" :: "l"(p))
#define PF_L1(p)         asm volatile("prefetch.global.L1 [%0];" :: "l"(p))

__device__ __forceinline__ float tanh_fast(float x) {
    float r; asm("tanh.approx.f32 %0, %1;" : "=f"(r) : "f"(x)); return r;
}
__device__ __forceinline__ uint64_t pk2(float lo, float hi) {
    uint64_t r; unsigned a = __float_as_uint(lo), b = __float_as_uint(hi);
    asm("mov.b64 %0, {%1, %2};" : "=l"(r) : "r"(a), "r"(b)); return r;
}
__device__ __forceinline__ float2 up2(uint64_t v) {
    unsigned a, b; asm("mov.b64 {%0, %1}, %2;" : "=r"(a), "=r"(b) : "l"(v));
    return make_float2(__uint_as_float(a), __uint_as_float(b));
}

__global__ void __launch_bounds__(256, 4) s_lstm_kernel(
    const float* __restrict__ x,
    const float* __restrict__ Wxi, const float* __restrict__ Wxf,
    const float* __restrict__ Wxc, const float* __restrict__ Wxo,
    const float* __restrict__ Whi, const float* __restrict__ Whf,
    const float* __restrict__ Whc, const float* __restrict__ Who,
    const float* __restrict__ Whsi, const float* __restrict__ Whsf,
    const float* __restrict__ Whsc, const float* __restrict__ Whso,
    const float* __restrict__ bi, const float* __restrict__ bf,
    const float* __restrict__ bc, const float* __restrict__ bo,
    float* __restrict__ out)
{
    __shared__ uint64_t sx2[TT];  // (xt, xt) pre-packed

    const int tid = threadIdx.x;
    const int idx = blockIdx.x * 256 + tid;  // r*H + c
    const int r = idx >> 10;                 // constant within a block
    const int c = idx & (HDIM - 1);

    if (tid < TT) {
        const float xt = x[tid * HDIM + r];
        sx2[tid] = pk2(xt, xt);
    }
    __syncthreads();

    // Warm L2 with every per-element weight line this thread will need.
#pragma unroll
    for (int l = 0; l < NL; l++) {
        PF_L2(Whi + l * HH + idx);
        PF_L2(Whf + l * HH + idx);
        PF_L2(Whc + l * HH + idx);
        PF_L2(Who + l * HH + idx);
    }
#pragma unroll
    for (int l = 0; l < NL - 1; l++) {
        PF_L2(Whsi + l * HH + idx);
        PF_L2(Whsf + l * HH + idx);
        PF_L2(Whsc + l * HH + idx);
        PF_L2(Whso + l * HH + idx);
    }

    // Packed poly constants for the (i,f) sigmoid pair.
    const uint64_t K2_2 = pk2(0.049435f, 0.049435f);
    const uint64_t K1_2 = pk2(-0.162927f, -0.162927f);
    const uint64_t K0_2 = pk2(0.499786f, 0.499786f);
    const uint64_t H5_2 = pk2(0.5f, 0.5f);

    // h of the layer below, per timestep (register array, fully unrolled use)
    float hb[TT];

    // ================= layer 0 (no skip; c0 = h0 = 0) =======================
    {
        // Pull next layer's weight lines toward L1 while layer 0 runs.
        PF_L1(Whi + HH + idx);  PF_L1(Whf + HH + idx);
        PF_L1(Whc + HH + idx);  PF_L1(Who + HH + idx);
        PF_L1(Whsi + idx);      PF_L1(Whsf + idx);
        PF_L1(Whsc + idx);      PF_L1(Whso + idx);

        const uint64_t Ax = pk2(0.5f * Wxi[c], 0.5f * Wxf[c]);
        const uint64_t Ay = pk2(0.5f * bi[c],  0.5f * bf[c]);
        const uint64_t Bx = pk2(0.5f * Wxo[c], Wxc[c]);
        const uint64_t By = pk2(0.5f * bo[c],  bc[c]);
        const uint64_t whif = pk2(0.5f * Whi[idx], 0.5f * Whf[idx]);
        const uint64_t whoc = pk2(0.5f * Who[idx], Whc[idx]);

        float cl = 0.0f, hl = 0.0f;
        float* pc = out + idx;                 // c plane, layer 0, t=0
        float* ph = pc + NL * HH;              // h plane

#pragma unroll
        for (int t = 0; t < TT; t++) {
            const uint64_t xt2 = sx2[t];       // broadcast LDS.64
            const uint64_t h2  = pk2(hl, hl);

            uint64_t zif, zoc;
            FMA2(zif, h2, whif, Ay);
            FMA2(zif, xt2, Ax, zif);
            FMA2(zoc, h2, whoc, By);
            FMA2(zoc, xt2, Bx, zoc);

            uint64_t s2, q2, sig2;
            MUL2(s2, zif, zif);
            FMA2(q2, s2, K2_2, K1_2);
            FMA2(q2, s2, q2, K0_2);
            FMA2(sig2, zif, q2, H5_2);
            const float2 igfg = up2(sig2);

            const float2 zocv = up2(zoc);                         // (zo/2, zc)
            const float og = fmaf(tanh_fast(zocv.x), 0.5f, 0.5f); // MUFU
            const float cc = tanh_fast(zocv.y);                   // MUFU

            const float cn = fmaf(igfg.y, cl, igfg.x * cc);
            const float hn = og * tanh_fast(cn);                  // MUFU
            cl = cn;
            hl = hn;
            hb[t] = hn;

            __stcs(pc, cn);
            __stcs(ph, hn);
            pc += 2 * NL * HH;
            ph += 2 * NL * HH;
        }
    }

    // ================= layers 1..3 ==========================================
#pragma unroll 1
    for (int l = 1; l < NL; l++) {
        if (l < NL - 1) {  // prefetch next layer's lines into L1
            PF_L1(Whi + (l + 1) * HH + idx);  PF_L1(Whf + (l + 1) * HH + idx);
            PF_L1(Whc + (l + 1) * HH + idx);  PF_L1(Who + (l + 1) * HH + idx);
            PF_L1(Whsi + l * HH + idx);       PF_L1(Whsf + l * HH + idx);
            PF_L1(Whsc + l * HH + idx);       PF_L1(Whso + l * HH + idx);
        }

        const uint64_t Ax = pk2(0.5f * Wxi[l * HDIM + c], 0.5f * Wxf[l * HDIM + c]);
        const uint64_t Ay = pk2(0.5f * bi[l * HDIM + c],  0.5f * bf[l * HDIM + c]);
        const uint64_t Bx = pk2(0.5f * Wxo[l * HDIM + c], Wxc[l * HDIM + c]);
        const uint64_t By = pk2(0.5f * bo[l * HDIM + c],  bc[l * HDIM + c]);
        const uint64_t whif = pk2(0.5f * Whi[l * HH + idx], 0.5f * Whf[l * HH + idx]);
        const uint64_t whoc = pk2(0.5f * Who[l * HH + idx], Whc[l * HH + idx]);
        const uint64_t wsif = pk2(0.5f * Whsi[(l - 1) * HH + idx],
                                  0.5f * Whsf[(l - 1) * HH + idx]);
        const uint64_t wsoc = pk2(0.5f * Whso[(l - 1) * HH + idx],
                                  Whsc[(l - 1) * HH + idx]);

        float cl = 0.0f, hl = 0.0f;
        float* pc = out + idx + l * HH;        // c plane of this layer, t=0
        float* ph = pc + NL * HH;              // h plane

#pragma unroll
        for (int t = 0; t < TT; t++) {
            const uint64_t xt2 = sx2[t];       // broadcast LDS.64
            const uint64_t h2  = pk2(hl, hl);
            const uint64_t hb2 = pk2(hb[t], hb[t]);

            uint64_t zif, zoc;
            FMA2(zif, h2, whif, Ay);
            FMA2(zif, hb2, wsif, zif);
            FMA2(zif, xt2, Ax, zif);
            FMA2(zoc, h2, whoc, By);
            FMA2(zoc, hb2, wsoc, zoc);
            FMA2(zoc, xt2, Bx, zoc);

            uint64_t s2, q2, sig2;
            MUL2(s2, zif, zif);
            FMA2(q2, s2, K2_2, K1_2);
            FMA2(q2, s2, q2, K0_2);
            FMA2(sig2, zif, q2, H5_2);
            const float2 igfg = up2(sig2);

            const float2 zocv = up2(zoc);                         // (zo/2, zc)
            const float og = fmaf(tanh_fast(zocv.x), 0.5f, 0.5f); // MUFU
            const float cc = tanh_fast(zocv.y);                   // MUFU

            const float cn = fmaf(igfg.y, cl, igfg.x * cc);
            const float hn = og * tanh_fast(cn);                  // MUFU
            cl = cn;
            hl = hn;
            hb[t] = hn;  // expose to the layer above

            __stcs(pc, cn);
            __stcs(ph, hn);
            pc += 2 * NL * HH;
            ph += 2 * NL * HH;
        }
    }
}

extern "C" void kernel_launch(void* const* d_in, const int* in_sizes, int n_in,
                              void* d_out, int out_size) {
    const float* x    = (const float*)d_in[0];
    const float* Wxi  = (const float*)d_in[1];
    const float* Wxf  = (const float*)d_in[2];
    const float* Wxc  = (const float*)d_in[3];
    const float* Wxo  = (const float*)d_in[4];
    const float* Whi  = (const float*)d_in[5];
    const float* Whf  = (const float*)d_in[6];
    const float* Whc  = (const float*)d_in[7];
    const float* Who  = (const float*)d_in[8];
    const float* Whsi = (const float*)d_in[9];
    const float* Whsf = (const float*)d_in[10];
    const float* Whsc = (const float*)d_in[11];
    const float* Whso = (const float*)d_in[12];
    const float* bi   = (const float*)d_in[13];
    const float* bf   = (const float*)d_in[14];
    const float* bc   = (const float*)d_in[15];
    const float* bo   = (const float*)d_in[16];
    float* out = (float*)d_out;

    dim3 block(256);
    dim3 grid(HH / 256);  // 4096 blocks, one thread per (r,c)
    s_lstm_kernel<<<grid, block>>>(x, Wxi, Wxf, Wxc, Wxo,
                                   Whi, Whf, Whc, Who,
                                   Whsi, Whsf, Whsc, Whso,
                                   bi, bf, bc, bo, out);
}

// round 16
// speedup vs baseline: 1.0027x; 1.0027x over previous
#include <cuda_runtime.h>
#include <cstdint>

// S_LSTM: 4-layer elementwise LSTM over a 1024x1024 broadcast grid, T=16.
// One thread per (r,c). R15 = R12 champion (l-outer/t-inner, f32x2 gate
// pairing, layer-0 specialized) + L2 evict_last cache-policy on all
// per-element weight loads (112MB weights vs 126MB L2 -> resident across
// graph replays; 512MB output stream uses evict-first .cs stores).
// Fix vs R14: scalar loads need the createpolicy + ld.L2::cache_hint form.

#define TT 16
#define HDIM 1024
#define NL 4
#define HH (HDIM * HDIM)

#define FMA2(d, a, b, c) asm("fma.rn.f32x2 %0, %1, %2, %3;" : "=l"(d) : "l"(a), "l"(b), "l"(c))
#define MUL2(d, a, b)    asm("mul.rn.f32x2 %0, %1, %2;"     : "=l"(d) : "l"(a), "l"(b))

__device__ __forceinline__ float tanh_fast(float x) {
    float r; asm("tanh.approx.f32 %0, %1;" : "=f"(r) : "f"(x)); return r;
}
// L2 evict_last policy descriptor (uniform, made once per thread)
__device__ __forceinline__ uint64_t mk_policy() {
    uint64_t p;
    asm("createpolicy.fractional.L2::evict_last.b64 %0, 1.0;" : "=l"(p));
    return p;
}
// weight load with L2 evict_last cache hint
__device__ __forceinline__ float ldg_el(const float* p, uint64_t pol) {
    float v;
    asm("ld.global.nc.L2::cache_hint.f32 %0, [%1], %2;"
        : "=f"(v) : "l"(p), "l"(pol));
    return v;
}
__device__ __forceinline__ uint64_t pk2(float lo, float hi) {
    uint64_t r; unsigned a = __float_as_uint(lo), b = __float_as_uint(hi);
    asm("mov.b64 %0, {%1, %2};" : "=l"(r) : "r"(a), "r"(b)); return r;
}
__device__ __forceinline__ float2 up2(uint64_t v) {
    unsigned a, b; asm("mov.b64 {%0, %1}, %2;" : "=r"(a), "=r"(b) : "l"(v));
    return make_float2(__uint_as_float(a), __uint_as_float(b));
}

__global__ void __launch_bounds__(256, 4) s_lstm_kernel(
    const float* __restrict__ x,
    const float* __restrict__ Wxi, const float* __restrict__ Wxf,
    const float* __restrict__ Wxc, const float* __restrict__ Wxo,
    const float* __restrict__ Whi, const float* __restrict__ Whf,
    const float* __restrict__ Whc, const float* __restrict__ Who,
    const float* __restrict__ Whsi, const float* __restrict__ Whsf,
    const float* __restrict__ Whsc, const float* __restrict__ Whso,
    const float* __restrict__ bi, const float* __restrict__ bf,
    const float* __restrict__ bc, const float* __restrict__ bo,
    float* __restrict__ out)
{
    __shared__ uint64_t sx2[TT];  // (xt, xt) pre-packed

    const int tid = threadIdx.x;
    const int idx = blockIdx.x * 256 + tid;  // r*H + c
    const int r = idx >> 10;                 // constant within a block
    const int c = idx & (HDIM - 1);

    if (tid < TT) {
        const float xt = x[tid * HDIM + r];
        sx2[tid] = pk2(xt, xt);
    }
    __syncthreads();

    const uint64_t POL = mk_policy();

    // Packed poly constants for the (i,f) sigmoid pair.
    const uint64_t K2_2 = pk2(0.049435f, 0.049435f);
    const uint64_t K1_2 = pk2(-0.162927f, -0.162927f);
    const uint64_t K0_2 = pk2(0.499786f, 0.499786f);
    const uint64_t H5_2 = pk2(0.5f, 0.5f);

    // h of the layer below, per timestep (register array, fully unrolled use)
    float hb[TT];

    // ================= layer 0 (no skip; c0 = h0 = 0) =======================
    {
        const uint64_t Ax = pk2(0.5f * Wxi[c], 0.5f * Wxf[c]);
        const uint64_t Ay = pk2(0.5f * bi[c],  0.5f * bf[c]);
        const uint64_t Bx = pk2(0.5f * Wxo[c], Wxc[c]);
        const uint64_t By = pk2(0.5f * bo[c],  bc[c]);
        const uint64_t whif = pk2(0.5f * ldg_el(Whi + idx, POL),
                                  0.5f * ldg_el(Whf + idx, POL));
        const uint64_t whoc = pk2(0.5f * ldg_el(Who + idx, POL),
                                  ldg_el(Whc + idx, POL));

        float cl = 0.0f, hl = 0.0f;
        float* pc = out + idx;                 // c plane, layer 0, t=0
        float* ph = pc + NL * HH;              // h plane

#pragma unroll
        for (int t = 0; t < TT; t++) {
            const uint64_t xt2 = sx2[t];       // broadcast LDS.64
            const uint64_t h2  = pk2(hl, hl);

            uint64_t zif, zoc;
            FMA2(zif, h2, whif, Ay);
            FMA2(zif, xt2, Ax, zif);
            FMA2(zoc, h2, whoc, By);
            FMA2(zoc, xt2, Bx, zoc);

            uint64_t s2, q2, sig2;
            MUL2(s2, zif, zif);
            FMA2(q2, s2, K2_2, K1_2);
            FMA2(q2, s2, q2, K0_2);
            FMA2(sig2, zif, q2, H5_2);
            const float2 igfg = up2(sig2);

            const float2 zocv = up2(zoc);                         // (zo/2, zc)
            const float og = fmaf(tanh_fast(zocv.x), 0.5f, 0.5f); // MUFU
            const float cc = tanh_fast(zocv.y);                   // MUFU

            const float cn = fmaf(igfg.y, cl, igfg.x * cc);
            const float hn = og * tanh_fast(cn);                  // MUFU
            cl = cn;
            hl = hn;
            hb[t] = hn;

            __stcs(pc, cn);
            __stcs(ph, hn);
            pc += 2 * NL * HH;
            ph += 2 * NL * HH;
        }
    }

    // ================= layers 1..3 ==========================================
#pragma unroll 1
    for (int l = 1; l < NL; l++) {
        const uint64_t Ax = pk2(0.5f * Wxi[l * HDIM + c], 0.5f * Wxf[l * HDIM + c]);
        const uint64_t Ay = pk2(0.5f * bi[l * HDIM + c],  0.5f * bf[l * HDIM + c]);
        const uint64_t Bx = pk2(0.5f * Wxo[l * HDIM + c], Wxc[l * HDIM + c]);
        const uint64_t By = pk2(0.5f * bo[l * HDIM + c],  bc[l * HDIM + c]);
        const uint64_t whif = pk2(0.5f * ldg_el(Whi + l * HH + idx, POL),
                                  0.5f * ldg_el(Whf + l * HH + idx, POL));
        const uint64_t whoc = pk2(0.5f * ldg_el(Who + l * HH + idx, POL),
                                  ldg_el(Whc + l * HH + idx, POL));
        const uint64_t wsif = pk2(0.5f * ldg_el(Whsi + (l - 1) * HH + idx, POL),
                                  0.5f * ldg_el(Whsf + (l - 1) * HH + idx, POL));
        const uint64_t wsoc = pk2(0.5f * ldg_el(Whso + (l - 1) * HH + idx, POL),
                                  ldg_el(Whsc + (l - 1) * HH + idx, POL));

        float cl = 0.0f, hl = 0.0f;
        float* pc = out + idx + l * HH;        // c plane of this layer, t=0
        float* ph = pc + NL * HH;              // h plane

#pragma unroll
        for (int t = 0; t < TT; t++) {
            const uint64_t xt2 = sx2[t];       // broadcast LDS.64
            const uint64_t h2  = pk2(hl, hl);
            const uint64_t hb2 = pk2(hb[t], hb[t]);

            uint64_t zif, zoc;
            FMA2(zif, h2, whif, Ay);
            FMA2(zif, hb2, wsif, zif);
            FMA2(zif, xt2, Ax, zif);
            FMA2(zoc, h2, whoc, By);
            FMA2(zoc, hb2, wsoc, zoc);
            FMA2(zoc, xt2, Bx, zoc);

            uint64_t s2, q2, sig2;
            MUL2(s2, zif, zif);
            FMA2(q2, s2, K2_2, K1_2);
            FMA2(q2, s2, q2, K0_2);
            FMA2(sig2, zif, q2, H5_2);
            const float2 igfg = up2(sig2);

            const float2 zocv = up2(zoc);                         // (zo/2, zc)
            const float og = fmaf(tanh_fast(zocv.x), 0.5f, 0.5f); // MUFU
            const float cc = tanh_fast(zocv.y);                   // MUFU

            const float cn = fmaf(igfg.y, cl, igfg.x * cc);
            const float hn = og * tanh_fast(cn);                  // MUFU
            cl = cn;
            hl = hn;
            hb[t] = hn;  // expose to the layer above

            __stcs(pc, cn);
            __stcs(ph, hn);
            pc += 2 * NL * HH;
            ph += 2 * NL * HH;
        }
    }
}

extern "C" void kernel_launch(void* const* d_in, const int* in_sizes, int n_in,
                              void* d_out, int out_size) {
    const float* x    = (const float*)d_in[0];
    const float* Wxi  = (const float*)d_in[1];
    const float* Wxf  = (const float*)d_in[2];
    const float* Wxc  = (const float*)d_in[3];
    const float* Wxo  = (const float*)d_in[4];
    const float* Whi  = (const float*)d_in[5];
    const float* Whf  = (const float*)d_in[6];
    const float* Whc  = (const float*)d_in[7];
    const float* Who  = (const float*)d_in[8];
    const float* Whsi = (const float*)d_in[9];
    const float* Whsf = (const float*)d_in[10];
    const float* Whsc = (const float*)d_in[11];
    const float* Whso = (const float*)d_in[12];
    const float* bi   = (const float*)d_in[13];
    const float* bf   = (const float*)d_in[14];
    const float* bc   = (const float*)d_in[15];
    const float* bo   = (const float*)d_in[16];
    float* out = (float*)d_out;

    dim3 block(256);
    dim3 grid(HH / 256);  // 4096 blocks, one thread per (r,c)
    s_lstm_kernel<<<grid, block>>>(x, Wxi, Wxf, Wxc, Wxo,
                                   Whi, Whf, Whc, Who,
                                   Whsi, Whsf, Whsc, Whso,
                                   bi, bf, bc, bo, out);
}

// round 17
// speedup vs baseline: 1.0259x; 1.0232x over previous
#include <cuda_runtime.h>
#include <cstdint>

// S_LSTM: 4-layer elementwise LSTM over a 1024x1024 broadcast grid, T=16.
// One thread per (r,c). R16 = consolidation of the two best measured variants:
//   R12 champion structure (l-outer/t-inner, per-layer params t-invariant in
//   registers, f32x2 gate pairing, L2-prefetched weights, layer-0 specialized)
//   + R15's sx2 pre-packed (xt,xt) broadcast (one less ALU pack/layer-step).
// Kernel is at the measured DRAM floor (~5.7 TB/s for 624 MB mandatory
// traffic); RF fully consumed at 64 regs x 1024 threads, so occupancy is
// capped and further structural changes spill (R5/R6) or go neutral (R10/R11/R15).

#define TT 16
#define HDIM 1024
#define NL 4
#define HH (HDIM * HDIM)

#define FMA2(d, a, b, c) asm("fma.rn.f32x2 %0, %1, %2, %3;" : "=l"(d) : "l"(a), "l"(b), "l"(c))
#define MUL2(d, a, b)    asm("mul.rn.f32x2 %0, %1, %2;"     : "=l"(d) : "l"(a), "l"(b))
#define PF_L2(p)         asm volatile("prefetch.global.L2 [%0];" :: "l"(p))

__device__ __forceinline__ float tanh_fast(float x) {
    float r; asm("tanh.approx.f32 %0, %1;" : "=f"(r) : "f"(x)); return r;
}
__device__ __forceinline__ uint64_t pk2(float lo, float hi) {
    uint64_t r; unsigned a = __float_as_uint(lo), b = __float_as_uint(hi);
    asm("mov.b64 %0, {%1, %2};" : "=l"(r) : "r"(a), "r"(b)); return r;
}
__device__ __forceinline__ float2 up2(uint64_t v) {
    unsigned a, b; asm("mov.b64 {%0, %1}, %2;" : "=r"(a), "=r"(b) : "l"(v));
    return make_float2(__uint_as_float(a), __uint_as_float(b));
}

__global__ void __launch_bounds__(256, 4) s_lstm_kernel(
    const float* __restrict__ x,
    const float* __restrict__ Wxi, const float* __restrict__ Wxf,
    const float* __restrict__ Wxc, const float* __restrict__ Wxo,
    const float* __restrict__ Whi, const float* __restrict__ Whf,
    const float* __restrict__ Whc, const float* __restrict__ Who,
    const float* __restrict__ Whsi, const float* __restrict__ Whsf,
    const float* __restrict__ Whsc, const float* __restrict__ Whso,
    const float* __restrict__ bi, const float* __restrict__ bf,
    const float* __restrict__ bc, const float* __restrict__ bo,
    float* __restrict__ out)
{
    __shared__ uint64_t sx2[TT];  // (xt, xt) pre-packed

    const int tid = threadIdx.x;
    const int idx = blockIdx.x * 256 + tid;  // r*H + c
    const int r = idx >> 10;                 // constant within a block
    const int c = idx & (HDIM - 1);

    if (tid < TT) {
        const float xt = x[tid * HDIM + r];
        sx2[tid] = pk2(xt, xt);
    }
    __syncthreads();

    // Warm L2 with every per-element weight line this thread will need.
#pragma unroll
    for (int l = 0; l < NL; l++) {
        PF_L2(Whi + l * HH + idx);
        PF_L2(Whf + l * HH + idx);
        PF_L2(Whc + l * HH + idx);
        PF_L2(Who + l * HH + idx);
    }
#pragma unroll
    for (int l = 0; l < NL - 1; l++) {
        PF_L2(Whsi + l * HH + idx);
        PF_L2(Whsf + l * HH + idx);
        PF_L2(Whsc + l * HH + idx);
        PF_L2(Whso + l * HH + idx);
    }

    // Packed poly constants for the (i,f) sigmoid pair.
    const uint64_t K2_2 = pk2(0.049435f, 0.049435f);
    const uint64_t K1_2 = pk2(-0.162927f, -0.162927f);
    const uint64_t K0_2 = pk2(0.499786f, 0.499786f);
    const uint64_t H5_2 = pk2(0.5f, 0.5f);

    // h of the layer below, per timestep (register array, fully unrolled use)
    float hb[TT];

    // ================= layer 0 (no skip; c0 = h0 = 0) =======================
    {
        const uint64_t Ax = pk2(0.5f * Wxi[c], 0.5f * Wxf[c]);
        const uint64_t Ay = pk2(0.5f * bi[c],  0.5f * bf[c]);
        const uint64_t Bx = pk2(0.5f * Wxo[c], Wxc[c]);
        const uint64_t By = pk2(0.5f * bo[c],  bc[c]);
        const uint64_t whif = pk2(0.5f * Whi[idx], 0.5f * Whf[idx]);
        const uint64_t whoc = pk2(0.5f * Who[idx], Whc[idx]);

        float cl = 0.0f, hl = 0.0f;
        float* pc = out + idx;                 // c plane, layer 0, t=0
        float* ph = pc + NL * HH;              // h plane

#pragma unroll
        for (int t = 0; t < TT; t++) {
            const uint64_t xt2 = sx2[t];       // broadcast LDS.64, pre-packed
            const uint64_t h2  = pk2(hl, hl);

            uint64_t zif, zoc;
            FMA2(zif, h2, whif, Ay);
            FMA2(zif, xt2, Ax, zif);
            FMA2(zoc, h2, whoc, By);
            FMA2(zoc, xt2, Bx, zoc);

            uint64_t s2, q2, sig2;
            MUL2(s2, zif, zif);
            FMA2(q2, s2, K2_2, K1_2);
            FMA2(q2, s2, q2, K0_2);
            FMA2(sig2, zif, q2, H5_2);
            const float2 igfg = up2(sig2);

            const float2 zocv = up2(zoc);                         // (zo/2, zc)
            const float og = fmaf(tanh_fast(zocv.x), 0.5f, 0.5f); // MUFU
            const float cc = tanh_fast(zocv.y);                   // MUFU

            const float cn = fmaf(igfg.y, cl, igfg.x * cc);
            const float hn = og * tanh_fast(cn);                  // MUFU
            cl = cn;
            hl = hn;
            hb[t] = hn;

            __stcs(pc, cn);
            __stcs(ph, hn);
            pc += 2 * NL * HH;
            ph += 2 * NL * HH;
        }
    }

    // ================= layers 1..3 ==========================================
#pragma unroll 1
    for (int l = 1; l < NL; l++) {
        const uint64_t Ax = pk2(0.5f * Wxi[l * HDIM + c], 0.5f * Wxf[l * HDIM + c]);
        const uint64_t Ay = pk2(0.5f * bi[l * HDIM + c],  0.5f * bf[l * HDIM + c]);
        const uint64_t Bx = pk2(0.5f * Wxo[l * HDIM + c], Wxc[l * HDIM + c]);
        const uint64_t By = pk2(0.5f * bo[l * HDIM + c],  bc[l * HDIM + c]);
        const uint64_t whif = pk2(0.5f * Whi[l * HH + idx], 0.5f * Whf[l * HH + idx]);
        const uint64_t whoc = pk2(0.5f * Who[l * HH + idx], Whc[l * HH + idx]);
        const uint64_t wsif = pk2(0.5f * Whsi[(l - 1) * HH + idx],
                                  0.5f * Whsf[(l - 1) * HH + idx]);
        const uint64_t wsoc = pk2(0.5f * Whso[(l - 1) * HH + idx],
                                  Whsc[(l - 1) * HH + idx]);

        float cl = 0.0f, hl = 0.0f;
        float* pc = out + idx + l * HH;        // c plane of this layer, t=0
        float* ph = pc + NL * HH;              // h plane

#pragma unroll
        for (int t = 0; t < TT; t++) {
            const uint64_t xt2 = sx2[t];       // broadcast LDS.64, pre-packed
            const uint64_t h2  = pk2(hl, hl);
            const uint64_t hb2 = pk2(hb[t], hb[t]);

            uint64_t zif, zoc;
            FMA2(zif, h2, whif, Ay);
            FMA2(zif, hb2, wsif, zif);
            FMA2(zif, xt2, Ax, zif);
            FMA2(zoc, h2, whoc, By);
            FMA2(zoc, hb2, wsoc, zoc);
            FMA2(zoc, xt2, Bx, zoc);

            uint64_t s2, q2, sig2;
            MUL2(s2, zif, zif);
            FMA2(q2, s2, K2_2, K1_2);
            FMA2(q2, s2, q2, K0_2);
            FMA2(sig2, zif, q2, H5_2);
            const float2 igfg = up2(sig2);

            const float2 zocv = up2(zoc);                         // (zo/2, zc)
            const float og = fmaf(tanh_fast(zocv.x), 0.5f, 0.5f); // MUFU
            const float cc = tanh_fast(zocv.y);                   // MUFU

            const float cn = fmaf(igfg.y, cl, igfg.x * cc);
            const float hn = og * tanh_fast(cn);                  // MUFU
            cl = cn;
            hl = hn;
            hb[t] = hn;  // expose to the layer above

            __stcs(pc, cn);
            __stcs(ph, hn);
            pc += 2 * NL * HH;
            ph += 2 * NL * HH;
        }
    }
}

extern "C" void kernel_launch(void* const* d_in, const int* in_sizes, int n_in,
                              void* d_out, int out_size) {
    const float* x    = (const float*)d_in[0];
    const float* Wxi  = (const float*)d_in[1];
    const float* Wxf  = (const float*)d_in[2];
    const float* Wxc  = (const float*)d_in[3];
    const float* Wxo  = (const float*)d_in[4];
    const float* Whi  = (const float*)d_in[5];
    const float* Whf  = (const float*)d_in[6];
    const float* Whc  = (const float*)d_in[7];
    const float* Who  = (const float*)d_in[8];
    const float* Whsi = (const float*)d_in[9];
    const float* Whsf = (const float*)d_in[10];
    const float* Whsc = (const float*)d_in[11];
    const float* Whso = (const float*)d_in[12];
    const float* bi   = (const float*)d_in[13];
    const float* bf   = (const float*)d_in[14];
    const float* bc   = (const float*)d_in[15];
    const float* bo   = (const float*)d_in[16];
    float* out = (float*)d_out;

    dim3 block(256);
    dim3 grid(HH / 256);  // 4096 blocks, one thread per (r,c)
    s_lstm_kernel<<<grid, block>>>(x, Wxi, Wxf, Wxc, Wxo,
                                   Whi, Whf, Whc, Who,
                                   Whsi, Whsf, Whsc, Whso,
                                   bi, bf, bc, bo, out);
}